// round 2
// baseline (speedup 1.0000x reference)
#include <cuda_runtime.h>
#include <math.h>

#define BQ      1024      // query batch
#define D_IN    96
#define D_MAIN  512
#define D_BLOCK 1024
#define N_CAND  65536
#define N_CLS   10

// ---------------- scratch (static device globals; no allocation) ----------------
__device__ float g_ctxvals[(size_t)N_CAND * D_MAIN];   // 128 MB
__device__ float g_logits [(size_t)BQ * N_CAND];       // 256 MB (reused as exp-weights)
__device__ float g_qa     [BQ * D_MAIN];
__device__ float g_qb     [BQ * D_MAIN];
__device__ float g_h      [BQ * D_BLOCK];
__device__ float g_ctx    [BQ * D_MAIN];
__device__ float g_rowsum [BQ];

// ---------------- generic 128x128x8 SGEMM, 256 thr, 8x8 microtile ----------------
// A: row-major [M,K].  B: NN -> row-major [K,N]; NT (BT=true) -> row-major [N,K].
// Requires: M,N multiples of 128; K (and split chunk) multiples of 8. All true here.
template<bool BT, bool BIAS, bool RELU, bool SPLITK>
__global__ void __launch_bounds__(256) sgemm128(
    const float* __restrict__ A, const float* __restrict__ B,
    const float* __restrict__ bias, float* __restrict__ C,
    int M, int N, int K, float alpha, int kChunk)
{
    __shared__ float As[8][128];
    __shared__ float Bs[8][128];
    const int t  = threadIdx.x;
    const int m0 = blockIdx.y * 128;
    const int n0 = blockIdx.x * 128;

    int kStart = 0, kEnd = K;
    if (SPLITK) { kStart = blockIdx.z * kChunk; kEnd = min(K, kStart + kChunk); }

    const int arow = t >> 1;            // 0..127
    const int aseg = (t & 1) * 4;       // 0 or 4
    const int brow = t >> 5;            // 0..7   (NN path)
    const int bcol = (t & 31) * 4;      // 0..124 (NN path)

    const int ty = (t >> 4) * 8;        // row offset in tile
    const int tx = (t & 15) * 8;        // col offset in tile

    float acc[8][8];
    #pragma unroll
    for (int i = 0; i < 8; ++i)
        #pragma unroll
        for (int j = 0; j < 8; ++j) acc[i][j] = 0.f;

    for (int kk = kStart; kk < kEnd; kk += 8) {
        // A tile -> As[k][m] (transposed store)
        float4 va = *(const float4*)(A + (size_t)(m0 + arow) * K + kk + aseg);
        As[aseg + 0][arow] = va.x; As[aseg + 1][arow] = va.y;
        As[aseg + 2][arow] = va.z; As[aseg + 3][arow] = va.w;

        if (BT) {
            // B row-major [N,K]: same pattern as A, transposed store -> Bs[k][n]
            float4 vb = *(const float4*)(B + (size_t)(n0 + arow) * K + kk + aseg);
            Bs[aseg + 0][arow] = vb.x; Bs[aseg + 1][arow] = vb.y;
            Bs[aseg + 2][arow] = vb.z; Bs[aseg + 3][arow] = vb.w;
        } else {
            // B row-major [K,N]: direct store -> Bs[k][n]
            float4 vb = *(const float4*)(B + (size_t)(kk + brow) * N + n0 + bcol);
            *(float4*)&Bs[brow][bcol] = vb;
        }
        __syncthreads();

        #pragma unroll
        for (int k = 0; k < 8; ++k) {
            float ar[8], br[8];
            #pragma unroll
            for (int i = 0; i < 8; ++i) ar[i] = As[k][ty + i];
            #pragma unroll
            for (int j = 0; j < 8; ++j) br[j] = Bs[k][tx + j];
            #pragma unroll
            for (int i = 0; i < 8; ++i)
                #pragma unroll
                for (int j = 0; j < 8; ++j)
                    acc[i][j] = fmaf(ar[i], br[j], acc[i][j]);
        }
        __syncthreads();
    }

    #pragma unroll
    for (int i = 0; i < 8; ++i) {
        const size_t crow = (size_t)(m0 + ty + i) * N;
        #pragma unroll
        for (int j = 0; j < 8; ++j) {
            const int n = n0 + tx + j;
            float v = acc[i][j] * alpha;
            if (BIAS) v += bias[n];
            if (RELU) v = fmaxf(v, 0.f);
            if (SPLITK) atomicAdd(&C[crow + n], v);
            else        C[crow + n] = v;
        }
    }
}

// ---------------- row softmax: store unnormalized exp + row sum ----------------
__global__ void __launch_bounds__(256) softmax_exp_kernel(
    float* __restrict__ logits, float* __restrict__ rowsum)
{
    const int b = blockIdx.x;
    float4* row = (float4*)(logits + (size_t)b * N_CAND);
    const int n4 = N_CAND / 4;
    __shared__ float red[256];

    float m = -1e30f;
    for (int i = threadIdx.x; i < n4; i += 256) {
        float4 v = row[i];
        m = fmaxf(m, fmaxf(fmaxf(v.x, v.y), fmaxf(v.z, v.w)));
    }
    red[threadIdx.x] = m; __syncthreads();
    for (int s = 128; s; s >>= 1) {
        if (threadIdx.x < s) red[threadIdx.x] = fmaxf(red[threadIdx.x], red[threadIdx.x + s]);
        __syncthreads();
    }
    const float rmax = red[0];
    __syncthreads();

    float sum = 0.f;
    for (int i = threadIdx.x; i < n4; i += 256) {
        float4 v = row[i];
        v.x = __expf(v.x - rmax); v.y = __expf(v.y - rmax);
        v.z = __expf(v.z - rmax); v.w = __expf(v.w - rmax);
        sum += v.x + v.y + v.z + v.w;
        row[i] = v;
    }
    red[threadIdx.x] = sum; __syncthreads();
    for (int s = 128; s; s >>= 1) {
        if (threadIdx.x < s) red[threadIdx.x] += red[threadIdx.x + s];
        __syncthreads();
    }
    if (threadIdx.x == 0) rowsum[b] = red[0];
}

// ---------------- zero-fill (for split-K atomic accumulation) ----------------
__global__ void zero_kernel(float* __restrict__ p, int n)
{
    int i = blockIdx.x * 256 + threadIdx.x;
    if (i < n) p[i] = 0.f;
}

// ---------------- head: out = (q + ctx/rowsum) @ head_w + head_b ----------------
// 1 block per query row, 10 warps (one per class)
__global__ void __launch_bounds__(320) head_kernel(
    const float* __restrict__ q, const float* __restrict__ ctx,
    const float* __restrict__ rowsum,
    const float* __restrict__ hw, const float* __restrict__ hb,
    float* __restrict__ out)
{
    const int b    = blockIdx.x;
    const int warp = threadIdx.x >> 5;
    const int lane = threadIdx.x & 31;
    if (warp >= N_CLS) return;

    const float inv = 1.f / rowsum[b];
    float s = 0.f;
    #pragma unroll 4
    for (int d = lane; d < D_MAIN; d += 32)
        s += (q[b * D_MAIN + d] + ctx[b * D_MAIN + d] * inv) * hw[d * N_CLS + warp];

    #pragma unroll
    for (int off = 16; off; off >>= 1)
        s += __shfl_down_sync(0xFFFFFFFFu, s, off);

    if (lane == 0) out[b * N_CLS + warp] = s + hb[warp];
}

// ---------------- launch ----------------
extern "C" void kernel_launch(void* const* d_in, const int* in_sizes, int n_in,
                              void* d_out, int out_size)
{
    const float* x    = (const float*)d_in[0];
    const float* cand = (const float*)d_in[1];
    const float* w0   = (const float*)d_in[2];
    const float* b0   = (const float*)d_in[3];
    const float* w1   = (const float*)d_in[4];   // [2, 512, 1024]
    const float* b1   = (const float*)d_in[5];   // [2, 1024]
    const float* w2   = (const float*)d_in[6];   // [2, 1024, 512]
    const float* b2   = (const float*)d_in[7];   // [2, 512]
    const float* tw   = (const float*)d_in[8];
    const float* tb   = (const float*)d_in[9];
    const float* hw   = (const float*)d_in[10];
    const float* hb   = (const float*)d_in[11];
    float* out = (float*)d_out;

    float *qa, *qb, *h, *ctxv, *logits, *ctx, *rowsum;
    cudaGetSymbolAddress((void**)&qa,     g_qa);
    cudaGetSymbolAddress((void**)&qb,     g_qb);
    cudaGetSymbolAddress((void**)&h,      g_h);
    cudaGetSymbolAddress((void**)&ctxv,   g_ctxvals);
    cudaGetSymbolAddress((void**)&logits, g_logits);
    cudaGetSymbolAddress((void**)&ctx,    g_ctx);
    cudaGetSymbolAddress((void**)&rowsum, g_rowsum);

    const dim3 blk(256);
    const float scale = (float)(1.0 / (sqrt(512.0) * 0.2));

    // ---- query encoder ----
    // q = x @ w0 + b0            [1024,512], K=96
    sgemm128<false, true, false, false><<<dim3(D_MAIN/128, BQ/128), blk>>>(
        x, w0, b0, qa, BQ, D_MAIN, D_IN, 1.f, 0);
    // block 0: h = relu(q @ w1[0] + b1[0]); q = h @ w2[0] + b2[0]
    sgemm128<false, true, true, false><<<dim3(D_BLOCK/128, BQ/128), blk>>>(
        qa, w1, b1, h, BQ, D_BLOCK, D_MAIN, 1.f, 0);
    sgemm128<false, true, false, false><<<dim3(D_MAIN/128, BQ/128), blk>>>(
        h, w2, b2, qb, BQ, D_MAIN, D_BLOCK, 1.f, 0);
    // block 1
    sgemm128<false, true, true, false><<<dim3(D_BLOCK/128, BQ/128), blk>>>(
        qb, w1 + (size_t)D_MAIN * D_BLOCK, b1 + D_BLOCK, h, BQ, D_BLOCK, D_MAIN, 1.f, 0);
    sgemm128<false, true, false, false><<<dim3(D_MAIN/128, BQ/128), blk>>>(
        h, w2 + (size_t)D_BLOCK * D_MAIN, b2 + D_MAIN, qa, BQ, D_MAIN, D_BLOCK, 1.f, 0);

    // ---- candidate transformation: ctx_vals = cand @ trans_w + trans_b ----
    sgemm128<false, true, false, false><<<dim3(D_MAIN/128, N_CAND/128), blk>>>(
        cand, tw, tb, ctxv, N_CAND, D_MAIN, D_MAIN, 1.f, 0);

    // ---- logits = scale * (q @ cand^T)   (NT) ----
    sgemm128<true, false, false, false><<<dim3(N_CAND/128, BQ/128), blk>>>(
        qa, cand, nullptr, logits, BQ, N_CAND, D_MAIN, scale, 0);

    // ---- softmax (unnormalized exp in-place + row sums) ----
    softmax_exp_kernel<<<BQ, 256>>>(logits, rowsum);

    // ---- context = exp_weights @ ctx_vals  (split-K=32, atomic accumulate) ----
    zero_kernel<<<(BQ * D_MAIN + 255) / 256, 256>>>(ctx, BQ * D_MAIN);
    sgemm128<false, false, false, true><<<dim3(D_MAIN/128, BQ/128, 32), blk>>>(
        logits, ctxv, nullptr, ctx, BQ, D_MAIN, N_CAND, 1.f, N_CAND / 32);

    // ---- head: out = (q + context/rowsum) @ head_w + head_b ----
    head_kernel<<<BQ, 320>>>(qa, ctx, rowsum, hw, hb, out);
}

// round 6
// speedup vs baseline: 2.3485x; 2.3485x over previous
#include <cuda_runtime.h>
#include <math.h>
#include <stdint.h>

#define BQ      1024
#define D_IN    96
#define D_MAIN  512
#define D_BLOCK 1024
#define N_CAND  65536
#define N_CLS   10

// ---------------- scratch ----------------
__device__ float g_qa    [BQ * D_MAIN];
__device__ float g_qb    [BQ * D_MAIN];
__device__ float g_h     [BQ * D_BLOCK];
__device__ float g_ctx   [BQ * D_MAIN];
__device__ float g_rowsum[BQ];
__device__ float g_logits[(size_t)BQ * N_CAND];
__device__ float g_ctxvT [(size_t)D_MAIN * N_CAND];
__device__ float g_w0T   [D_MAIN * D_IN];
__device__ float g_w1T   [2 * D_BLOCK * D_MAIN];
__device__ float g_w2T   [2 * D_MAIN * D_BLOCK];
__device__ float g_twT   [D_MAIN * D_MAIN];

// ---------------- helpers ----------------
__device__ __forceinline__ uint32_t smem_u32(const void* p) {
    uint32_t a;
    asm("{ .reg .u64 t; cvta.to.shared.u64 t, %1; cvt.u32.u64 %0, t; }" : "=r"(a) : "l"(p));
    return a;
}
__device__ __forceinline__ uint32_t f2tf32(float f) {
    uint32_t u; asm("cvt.rna.tf32.f32 %0, %1;" : "=r"(u) : "f"(f)); return u;
}
#define CP_ASYNC(dst, src) \
    asm volatile("cp.async.cg.shared.global [%0], [%1], 16;" :: "r"(dst), "l"(src))
#define CP_COMMIT() asm volatile("cp.async.commit_group;")
#define LDMX4(r0, r1, r2, r3, a) \
    asm volatile("ldmatrix.sync.aligned.m8n8.x4.shared.b16 {%0,%1,%2,%3}, [%4];" \
                 : "=r"(r0), "=r"(r1), "=r"(r2), "=r"(r3) : "r"(a))
#define MMA(d, a, b0, b1) \
    asm volatile("mma.sync.aligned.m16n8k8.row.col.f32.tf32.tf32.f32 " \
                 "{%0,%1,%2,%3}, {%4,%5,%6,%7}, {%8,%9}, {%0,%1,%2,%3};" \
                 : "+f"((d)[0]), "+f"((d)[1]), "+f"((d)[2]), "+f"((d)[3]) \
                 : "r"((a)[0]), "r"((a)[1]), "r"((a)[2]), "r"((a)[3]), "r"(b0), "r"(b1))

// ---------------- universal NT tf32 mma.sync GEMM ----------------
// D[M,N] = alpha * A[M,K] @ B[N,K]^T (+bias)(relu). Tile 128x128, BK=16.
// grid = (M/128, N/128, splitZ). THREE => 3xTF32 error-compensated.
// smem: 2 stages x (A 128x20f + B 128x20f) = 40960B. ldmatrix conflict-free via 20f pad.
template<bool THREE, bool BIAS, bool RELU, bool TROUT, bool ATOMIC>
__global__ void __launch_bounds__(256, 2) mma_nt(
    const float* __restrict__ A, const float* __restrict__ B,
    const float* __restrict__ bias, float* __restrict__ C,
    int lda, int ldb, int ldc, int nch, float alpha)
{
    __shared__ float smem[2 * 5120];      // stage: A[128*20] then B[128*20]
    const uint32_t sb = smem_u32(smem);
    const int tid  = threadIdx.x;
    const int wid  = tid >> 5;
    const int lane = tid & 31;
    const int m0 = blockIdx.x * 128;
    const int n0 = blockIdx.y * 128;
    const int warp_m = (wid >> 2) * 64;
    const int warp_n = (wid & 3) * 32;

    A += (size_t)blockIdx.z * nch * 16;
    B += (size_t)blockIdx.z * nch * 16;

    const float* Abase = A + (size_t)m0 * lda;
    const float* Bbase = B + (size_t)n0 * ldb;

    // cp.async mapping: 2 chunks of A + 2 of B per thread per stage
    const int r0c = tid >> 2,         s0c = (tid & 3) * 4;
    const int r1c = (tid + 256) >> 2, s1c = ((tid + 256) & 3) * 4;

    float acc[4][4][4];
    #pragma unroll
    for (int i = 0; i < 4; ++i)
        #pragma unroll
        for (int j = 0; j < 4; ++j)
            #pragma unroll
            for (int k = 0; k < 4; ++k) acc[i][j][k] = 0.f;

    // ldmatrix base addresses (lane-dependent)
    const uint32_t aOff = ((warp_m + (lane & 15)) * 20 + (lane >> 4) * 4) * 4;
    const uint32_t bOff = ((warp_n + ((lane >> 4) << 3) + (lane & 7)) * 20 +
                           ((lane >> 3) & 1) * 4) * 4;

    // prologue: stage 0, chunk 0
    {
        CP_ASYNC(sb + (r0c * 20 + s0c) * 4,        Abase + (size_t)r0c * lda + s0c);
        CP_ASYNC(sb + (r1c * 20 + s1c) * 4,        Abase + (size_t)r1c * lda + s1c);
        CP_ASYNC(sb + (2560 + r0c * 20 + s0c) * 4, Bbase + (size_t)r0c * ldb + s0c);
        CP_ASYNC(sb + (2560 + r1c * 20 + s1c) * 4, Bbase + (size_t)r1c * ldb + s1c);
        CP_COMMIT();
    }

    int st = 0;
    for (int c = 0; c < nch; ++c) {
        if (c + 1 < nch) {
            const int k0 = (c + 1) * 16;
            const uint32_t s = sb + (st ^ 1) * 5120 * 4;
            CP_ASYNC(s + (r0c * 20 + s0c) * 4,        Abase + (size_t)r0c * lda + k0 + s0c);
            CP_ASYNC(s + (r1c * 20 + s1c) * 4,        Abase + (size_t)r1c * lda + k0 + s1c);
            CP_ASYNC(s + (2560 + r0c * 20 + s0c) * 4, Bbase + (size_t)r0c * ldb + k0 + s0c);
            CP_ASYNC(s + (2560 + r1c * 20 + s1c) * 4, Bbase + (size_t)r1c * ldb + k0 + s1c);
            CP_COMMIT();
            asm volatile("cp.async.wait_group 1;");
        } else {
            asm volatile("cp.async.wait_group 0;");
        }
        __syncthreads();

        const uint32_t aB = sb + st * 5120 * 4 + aOff;
        const uint32_t bB = sb + (st * 5120 + 2560) * 4 + bOff;

        #pragma unroll
        for (int ks = 0; ks < 2; ++ks) {
            uint32_t br[8], bh[8], bl[8];
            LDMX4(br[0], br[1], br[2], br[3], bB + ks * 32);
            LDMX4(br[4], br[5], br[6], br[7], bB + 1280 + ks * 32);
            #pragma unroll
            for (int i = 0; i < 8; ++i) {
                const float f = __uint_as_float(br[i]);
                bh[i] = f2tf32(f);
                if (THREE) bl[i] = f2tf32(f - __uint_as_float(bh[i]));
            }
            #pragma unroll
            for (int mi = 0; mi < 4; ++mi) {
                uint32_t ar[4], ah[4], al[4];
                LDMX4(ar[0], ar[1], ar[2], ar[3], aB + mi * 1280 + ks * 32);
                #pragma unroll
                for (int i = 0; i < 4; ++i) {
                    const float f = __uint_as_float(ar[i]);
                    ah[i] = f2tf32(f);
                    if (THREE) al[i] = f2tf32(f - __uint_as_float(ah[i]));
                }
                #pragma unroll
                for (int ni = 0; ni < 4; ++ni) {
                    MMA(acc[mi][ni], ah, bh[ni * 2], bh[ni * 2 + 1]);
                    if (THREE) {
                        MMA(acc[mi][ni], al, bh[ni * 2], bh[ni * 2 + 1]);
                        MMA(acc[mi][ni], ah, bl[ni * 2], bl[ni * 2 + 1]);
                    }
                }
            }
        }
        __syncthreads();
        st ^= 1;
    }

    // ---------------- epilogue ----------------
    #pragma unroll
    for (int mi = 0; mi < 4; ++mi) {
        const int rg = m0 + warp_m + mi * 16 + (lane >> 2);
        #pragma unroll
        for (int ni = 0; ni < 4; ++ni) {
            const int cg = n0 + warp_n + ni * 8 + (lane & 3) * 2;
            float b0v = 0.f, b1v = 0.f;
            if (BIAS) { b0v = bias[cg]; b1v = bias[cg + 1]; }
            float v0 = acc[mi][ni][0] * alpha + b0v;
            float v1 = acc[mi][ni][1] * alpha + b1v;
            float v2 = acc[mi][ni][2] * alpha + b0v;
            float v3 = acc[mi][ni][3] * alpha + b1v;
            if (RELU) {
                v0 = fmaxf(v0, 0.f); v1 = fmaxf(v1, 0.f);
                v2 = fmaxf(v2, 0.f); v3 = fmaxf(v3, 0.f);
            }
            if (TROUT) {
                C[(size_t)cg * ldc + rg]           = v0;
                C[(size_t)(cg + 1) * ldc + rg]     = v1;
                C[(size_t)cg * ldc + rg + 8]       = v2;
                C[(size_t)(cg + 1) * ldc + rg + 8] = v3;
            } else if (ATOMIC) {
                atomicAdd(&C[(size_t)rg * ldc + cg],           v0);
                atomicAdd(&C[(size_t)rg * ldc + cg + 1],       v1);
                atomicAdd(&C[(size_t)(rg + 8) * ldc + cg],     v2);
                atomicAdd(&C[(size_t)(rg + 8) * ldc + cg + 1], v3);
            } else {
                float2 p0 = make_float2(v0, v1);
                float2 p1 = make_float2(v2, v3);
                *(float2*)&C[(size_t)rg * ldc + cg]       = p0;
                *(float2*)&C[(size_t)(rg + 8) * ldc + cg] = p1;
            }
        }
    }
}

// ---------------- transpose out[C][R] = in[R][C]^T ----------------
__global__ void transpose_k(const float* __restrict__ in, float* __restrict__ out, int R, int C)
{
    __shared__ float t[32][33];
    const int c0 = blockIdx.x * 32, r0 = blockIdx.y * 32;
    #pragma unroll
    for (int j = 0; j < 32; j += 8) {
        int r = r0 + threadIdx.y + j, c = c0 + threadIdx.x;
        if (r < R && c < C) t[threadIdx.y + j][threadIdx.x] = in[(size_t)r * C + c];
    }
    __syncthreads();
    #pragma unroll
    for (int j = 0; j < 32; j += 8) {
        int r = c0 + threadIdx.y + j, c = r0 + threadIdx.x;
        if (r < C && c < R) out[(size_t)r * R + c] = t[threadIdx.x][threadIdx.y + j];
    }
}

// ---------------- softmax: unnormalized exp in-place + row sums ----------------
__global__ void __launch_bounds__(256) softmax_exp_kernel(
    float* __restrict__ logits, float* __restrict__ rowsum)
{
    const int b = blockIdx.x;
    float4* row = (float4*)(logits + (size_t)b * N_CAND);
    const int n4 = N_CAND / 4;
    __shared__ float red[256];
    float m = -1e30f;
    for (int i = threadIdx.x; i < n4; i += 256) {
        float4 v = row[i];
        m = fmaxf(m, fmaxf(fmaxf(v.x, v.y), fmaxf(v.z, v.w)));
    }
    red[threadIdx.x] = m; __syncthreads();
    for (int s = 128; s; s >>= 1) {
        if (threadIdx.x < s) red[threadIdx.x] = fmaxf(red[threadIdx.x], red[threadIdx.x + s]);
        __syncthreads();
    }
    const float rmax = red[0];
    __syncthreads();
    float sum = 0.f;
    for (int i = threadIdx.x; i < n4; i += 256) {
        float4 v = row[i];
        v.x = __expf(v.x - rmax); v.y = __expf(v.y - rmax);
        v.z = __expf(v.z - rmax); v.w = __expf(v.w - rmax);
        sum += v.x + v.y + v.z + v.w;
        row[i] = v;
    }
    red[threadIdx.x] = sum; __syncthreads();
    for (int s = 128; s; s >>= 1) {
        if (threadIdx.x < s) red[threadIdx.x] += red[threadIdx.x + s];
        __syncthreads();
    }
    if (threadIdx.x == 0) rowsum[b] = red[0];
}

__global__ void zero_kernel(float* __restrict__ p, int n)
{
    int i = blockIdx.x * 256 + threadIdx.x;
    if (i < n) p[i] = 0.f;
}

// ---------------- head ----------------
__global__ void __launch_bounds__(320) head_kernel(
    const float* __restrict__ q, const float* __restrict__ ctx,
    const float* __restrict__ rowsum, const float* __restrict__ hw,
    const float* __restrict__ hb, float* __restrict__ out)
{
    const int b = blockIdx.x;
    const int warp = threadIdx.x >> 5;
    const int lane = threadIdx.x & 31;
    if (warp >= N_CLS) return;
    const float inv = 1.f / rowsum[b];
    float s = 0.f;
    #pragma unroll 4
    for (int d = lane; d < D_MAIN; d += 32)
        s += (q[b * D_MAIN + d] + ctx[b * D_MAIN + d] * inv) * hw[d * N_CLS + warp];
    #pragma unroll
    for (int off = 16; off; off >>= 1) s += __shfl_down_sync(0xFFFFFFFFu, s, off);
    if (lane == 0) out[b * N_CLS + warp] = s + hb[warp];
}

// ---------------- launch ----------------
extern "C" void kernel_launch(void* const* d_in, const int* in_sizes, int n_in,
                              void* d_out, int out_size)
{
    const float* x    = (const float*)d_in[0];
    const float* cand = (const float*)d_in[1];
    const float* w0   = (const float*)d_in[2];
    const float* b0   = (const float*)d_in[3];
    const float* w1   = (const float*)d_in[4];
    const float* b1   = (const float*)d_in[5];
    const float* w2   = (const float*)d_in[6];
    const float* b2   = (const float*)d_in[7];
    const float* tw   = (const float*)d_in[8];
    const float* tb   = (const float*)d_in[9];
    const float* hw   = (const float*)d_in[10];
    const float* hb   = (const float*)d_in[11];
    float* out = (float*)d_out;

    float *qa, *qb, *h, *ctx, *rowsum, *logits, *ctxvT, *w0T, *w1T, *w2T, *twT;
    cudaGetSymbolAddress((void**)&qa, g_qa);
    cudaGetSymbolAddress((void**)&qb, g_qb);
    cudaGetSymbolAddress((void**)&h, g_h);
    cudaGetSymbolAddress((void**)&ctx, g_ctx);
    cudaGetSymbolAddress((void**)&rowsum, g_rowsum);
    cudaGetSymbolAddress((void**)&logits, g_logits);
    cudaGetSymbolAddress((void**)&ctxvT, g_ctxvT);
    cudaGetSymbolAddress((void**)&w0T, g_w0T);
    cudaGetSymbolAddress((void**)&w1T, g_w1T);
    cudaGetSymbolAddress((void**)&w2T, g_w2T);
    cudaGetSymbolAddress((void**)&twT, g_twT);

    const float scale = (float)(1.0 / (sqrt(512.0) * 0.2));
    dim3 tb32(32, 8);

    // weight transposes
    transpose_k<<<dim3(16, 3), tb32>>>(w0, w0T, D_IN, D_MAIN);
    transpose_k<<<dim3(32, 16), tb32>>>(w1, w1T, D_MAIN, D_BLOCK);
    transpose_k<<<dim3(32, 16), tb32>>>(w1 + D_MAIN*D_BLOCK, w1T + D_BLOCK*D_MAIN, D_MAIN, D_BLOCK);
    transpose_k<<<dim3(16, 32), tb32>>>(w2, w2T, D_BLOCK, D_MAIN);
    transpose_k<<<dim3(16, 32), tb32>>>(w2 + D_BLOCK*D_MAIN, w2T + D_MAIN*D_BLOCK, D_BLOCK, D_MAIN);
    transpose_k<<<dim3(16, 16), tb32>>>(tw, twT, D_MAIN, D_MAIN);

    // encoder (3xTF32)
    mma_nt<true,true,false,false,false><<<dim3(8,4), 256>>>(
        x, w0T, b0, qa, D_IN, D_IN, D_MAIN, 6, 1.f);
    mma_nt<true,true,true,false,false><<<dim3(8,8), 256>>>(
        qa, w1T, b1, h, D_MAIN, D_MAIN, D_BLOCK, 32, 1.f);
    mma_nt<true,true,false,false,false><<<dim3(8,4), 256>>>(
        h, w2T, b2, qb, D_BLOCK, D_BLOCK, D_MAIN, 64, 1.f);
    mma_nt<true,true,true,false,false><<<dim3(8,8), 256>>>(
        qb, w1T + D_BLOCK*D_MAIN, b1 + D_BLOCK, h, D_MAIN, D_MAIN, D_BLOCK, 32, 1.f);
    mma_nt<true,true,false,false,false><<<dim3(8,4), 256>>>(
        h, w2T + D_MAIN*D_BLOCK, b2 + D_MAIN, qa, D_BLOCK, D_BLOCK, D_MAIN, 64, 1.f);

    // ctx_vals^T = (cand @ tw + tb)^T  (single tf32, transposed epilogue)
    mma_nt<false,true,false,true,false><<<dim3(512,4), 256>>>(
        cand, twT, tb, ctxvT, D_MAIN, D_MAIN, N_CAND, 32, 1.f);

    // logits = scale * q @ cand^T  (3xTF32)
    mma_nt<true,false,false,false,false><<<dim3(8,512), 256>>>(
        qa, cand, nullptr, logits, D_MAIN, D_MAIN, N_CAND, 32, scale);

    // softmax (unnormalized) + row sums
    softmax_exp_kernel<<<BQ, 256>>>(logits, rowsum);

    // context = expw @ (ctxvT)^T   (split-K=32, atomic accumulate)
    zero_kernel<<<(BQ * D_MAIN + 255) / 256, 256>>>(ctx, BQ * D_MAIN);
    mma_nt<false,false,false,false,true><<<dim3(8,4,32), 256>>>(
        logits, ctxvT, nullptr, ctx, N_CAND, N_CAND, D_MAIN, 128, 1.f);

    // head
    head_kernel<<<BQ, 320>>>(qa, ctx, rowsum, hw, hb, out);
}

// round 7
// speedup vs baseline: 2.7249x; 1.1603x over previous
#include <cuda_runtime.h>
#include <cuda_bf16.h>
#include <math.h>
#include <stdint.h>

#define BQ      1024
#define D_IN    96
#define D_MAIN  512
#define D_BLOCK 1024
#define N_CAND  65536
#define N_CLS   10

// ---------------- scratch ----------------
__device__ float g_qa    [BQ * D_MAIN];
__device__ float g_qb    [BQ * D_MAIN];
__device__ float g_h     [BQ * D_BLOCK];
__device__ float g_ctx   [BQ * D_MAIN];
__device__ float g_rowsum[BQ];
__device__ float g_logits[(size_t)BQ * N_CAND];
__device__ float g_ctxvT [(size_t)D_MAIN * N_CAND];
__device__ float g_w0T   [D_MAIN * D_IN];
__device__ float g_w1T   [2 * D_BLOCK * D_MAIN];
__device__ float g_w2T   [2 * D_MAIN * D_BLOCK];
__device__ float g_twT   [D_MAIN * D_MAIN];
// bf16 hi/lo decompositions
__device__ __nv_bfloat16 g_candH[(size_t)N_CAND * D_MAIN];
__device__ __nv_bfloat16 g_candL[(size_t)N_CAND * D_MAIN];
__device__ __nv_bfloat16 g_xH[BQ * D_IN],            g_xL[BQ * D_IN];
__device__ __nv_bfloat16 g_w0TH[D_MAIN * D_IN],      g_w0TL[D_MAIN * D_IN];
__device__ __nv_bfloat16 g_w1TH[2 * D_BLOCK * D_MAIN], g_w1TL[2 * D_BLOCK * D_MAIN];
__device__ __nv_bfloat16 g_w2TH[2 * D_MAIN * D_BLOCK], g_w2TL[2 * D_MAIN * D_BLOCK];
__device__ __nv_bfloat16 g_aH[BQ * D_MAIN],          g_aL[BQ * D_MAIN];     // q-act split
__device__ __nv_bfloat16 g_hH[BQ * D_BLOCK],         g_hL[BQ * D_BLOCK];    // h-act split

// ---------------- helpers ----------------
__device__ __forceinline__ uint32_t smem_u32(const void* p) {
    uint32_t a;
    asm("{ .reg .u64 t; cvta.to.shared.u64 t, %1; cvt.u32.u64 %0, t; }" : "=r"(a) : "l"(p));
    return a;
}
__device__ __forceinline__ uint32_t f2tf32(float f) {
    uint32_t u; asm("cvt.rna.tf32.f32 %0, %1;" : "=r"(u) : "f"(f)); return u;
}
#define CP_ASYNC(dst, src) \
    asm volatile("cp.async.cg.shared.global [%0], [%1], 16;" :: "r"(dst), "l"(src))
#define CP_COMMIT() asm volatile("cp.async.commit_group;")
#define LDMX4(r0, r1, r2, r3, a) \
    asm volatile("ldmatrix.sync.aligned.m8n8.x4.shared.b16 {%0,%1,%2,%3}, [%4];" \
                 : "=r"(r0), "=r"(r1), "=r"(r2), "=r"(r3) : "r"(a))
#define MMA(d, a, b0, b1) \
    asm volatile("mma.sync.aligned.m16n8k8.row.col.f32.tf32.tf32.f32 " \
                 "{%0,%1,%2,%3}, {%4,%5,%6,%7}, {%8,%9}, {%0,%1,%2,%3};" \
                 : "+f"((d)[0]), "+f"((d)[1]), "+f"((d)[2]), "+f"((d)[3]) \
                 : "r"((a)[0]), "r"((a)[1]), "r"((a)[2]), "r"((a)[3]), "r"(b0), "r"(b1))
#define MMA16(d, a, b0, b1) \
    asm volatile("mma.sync.aligned.m16n8k16.row.col.f32.bf16.bf16.f32 " \
                 "{%0,%1,%2,%3}, {%4,%5,%6,%7}, {%8,%9}, {%0,%1,%2,%3};" \
                 : "+f"((d)[0]), "+f"((d)[1]), "+f"((d)[2]), "+f"((d)[3]) \
                 : "r"((a)[0]), "r"((a)[1]), "r"((a)[2]), "r"((a)[3]), "r"(b0), "r"(b1))

// ---------------- split: fp32 -> bf16 hi + bf16 lo ----------------
__global__ void split_k(const float* __restrict__ in, __nv_bfloat16* __restrict__ hi,
                        __nv_bfloat16* __restrict__ lo, int n4)
{
    int i = blockIdx.x * 256 + threadIdx.x;
    if (i >= n4) return;
    float4 v = ((const float4*)in)[i];
    ushort4 hv, lv;
    __nv_bfloat16 h;
    h = __float2bfloat16_rn(v.x); hv.x = __bfloat16_as_ushort(h);
    lv.x = __bfloat16_as_ushort(__float2bfloat16_rn(v.x - __bfloat162float(h)));
    h = __float2bfloat16_rn(v.y); hv.y = __bfloat16_as_ushort(h);
    lv.y = __bfloat16_as_ushort(__float2bfloat16_rn(v.y - __bfloat162float(h)));
    h = __float2bfloat16_rn(v.z); hv.z = __bfloat16_as_ushort(h);
    lv.z = __bfloat16_as_ushort(__float2bfloat16_rn(v.z - __bfloat162float(h)));
    h = __float2bfloat16_rn(v.w); hv.w = __bfloat16_as_ushort(h);
    lv.w = __bfloat16_as_ushort(__float2bfloat16_rn(v.w - __bfloat162float(h)));
    ((ushort4*)hi)[i] = hv;
    ((ushort4*)lo)[i] = lv;
}

// ---------------- bf16x3 NT GEMM: D = alpha*(AH+AL)(BH+BL)^T (+bias)(relu) ----------------
// D[M,N], A[M,K], B[N,K] as bf16 hi/lo pairs. Tile 128x128, BK=16, m16n8k16 bf16 mma.
// 3 passes: AH*BH + AL*BH + AH*BL  (missing AL*BL ~ 2^-16).
// smem/stage: AH,AL,BH,BL tiles of 128 rows x 48B (16 bf16 + 8 pad) = 4x6144; 2 stages = 49152B.
template<bool BIAS, bool RELU>
__global__ void __launch_bounds__(256) mma_bf16_nt(
    const __nv_bfloat16* __restrict__ AH, const __nv_bfloat16* __restrict__ AL,
    const __nv_bfloat16* __restrict__ BH, const __nv_bfloat16* __restrict__ BL,
    const float* __restrict__ bias, float* __restrict__ C,
    int lda, int ldb, int ldc, int nch, float alpha)
{
    __shared__ char smem[49152];
    const uint32_t sb = smem_u32(smem);
    const int tid  = threadIdx.x;
    const int wid  = tid >> 5;
    const int lane = tid & 31;
    const int m0 = blockIdx.x * 128;
    const int n0 = blockIdx.y * 128;
    const int warp_m = (wid >> 2) * 64;
    const int warp_n = (wid & 3) * 32;

    const __nv_bfloat16* ah = AH + (size_t)m0 * lda;
    const __nv_bfloat16* al = AL + (size_t)m0 * lda;
    const __nv_bfloat16* bh = BH + (size_t)n0 * ldb;
    const __nv_bfloat16* bl = BL + (size_t)n0 * ldb;

    // staging: each thread copies one 16B chunk into each of the 4 tiles
    const int rr = tid >> 1;               // row 0..127
    const int he = (tid & 1) * 8;          // element offset (8 bf16 = 16B)
    const uint32_t sOff = rr * 48 + (tid & 1) * 16;

    float acc[4][4][4];
    #pragma unroll
    for (int i = 0; i < 4; ++i)
        #pragma unroll
        for (int j = 0; j < 4; ++j)
            #pragma unroll
            for (int k = 0; k < 4; ++k) acc[i][j][k] = 0.f;

    // ldmatrix lane pattern (natural b16): row = base + (lane&15), byte = (lane>>4)*16
    const uint32_t lOff = (uint32_t)(lane & 15) * 48 + (uint32_t)(lane >> 4) * 16;
    const uint32_t aO = (uint32_t)warp_m * 48 + lOff;
    const uint32_t bO = (uint32_t)warp_n * 48 + lOff;

    // prologue
    {
        CP_ASYNC(sb + sOff,         ah + (size_t)rr * lda + he);
        CP_ASYNC(sb + 6144 + sOff,  al + (size_t)rr * lda + he);
        CP_ASYNC(sb + 12288 + sOff, bh + (size_t)rr * ldb + he);
        CP_ASYNC(sb + 18432 + sOff, bl + (size_t)rr * ldb + he);
        CP_COMMIT();
    }

    int st = 0;
    for (int c = 0; c < nch; ++c) {
        if (c + 1 < nch) {
            const int k0 = (c + 1) * 16;
            const uint32_t s = sb + (st ^ 1) * 24576;
            CP_ASYNC(s + sOff,         ah + (size_t)rr * lda + k0 + he);
            CP_ASYNC(s + 6144 + sOff,  al + (size_t)rr * lda + k0 + he);
            CP_ASYNC(s + 12288 + sOff, bh + (size_t)rr * ldb + k0 + he);
            CP_ASYNC(s + 18432 + sOff, bl + (size_t)rr * ldb + k0 + he);
            CP_COMMIT();
            asm volatile("cp.async.wait_group 1;");
        } else {
            asm volatile("cp.async.wait_group 0;");
        }
        __syncthreads();

        const uint32_t base = sb + st * 24576;
        // B fragments: two x4 per tile cover n0-15 / n16-31
        uint32_t bhr[8], blr[8];
        LDMX4(bhr[0], bhr[1], bhr[2], bhr[3], base + 12288 + bO);
        LDMX4(bhr[4], bhr[5], bhr[6], bhr[7], base + 12288 + bO + 768);
        LDMX4(blr[0], blr[1], blr[2], blr[3], base + 18432 + bO);
        LDMX4(blr[4], blr[5], blr[6], blr[7], base + 18432 + bO + 768);

        #pragma unroll
        for (int mi = 0; mi < 4; ++mi) {
            uint32_t ahf[4], alf[4];
            LDMX4(ahf[0], ahf[1], ahf[2], ahf[3], base + aO + mi * 768);
            LDMX4(alf[0], alf[1], alf[2], alf[3], base + 6144 + aO + mi * 768);
            #pragma unroll
            for (int ni = 0; ni < 4; ++ni) {
                const int g = (ni >> 1) * 4, s2 = ni & 1;
                const uint32_t b0h = bhr[g + s2], b1h = bhr[g + s2 + 2];
                const uint32_t b0l = blr[g + s2], b1l = blr[g + s2 + 2];
                MMA16(acc[mi][ni], ahf, b0h, b1h);
                MMA16(acc[mi][ni], alf, b0h, b1h);
                MMA16(acc[mi][ni], ahf, b0l, b1l);
            }
        }
        __syncthreads();
        st ^= 1;
    }

    // epilogue (same m16n8 C layout)
    #pragma unroll
    for (int mi = 0; mi < 4; ++mi) {
        const int rg = m0 + warp_m + mi * 16 + (lane >> 2);
        #pragma unroll
        for (int ni = 0; ni < 4; ++ni) {
            const int cg = n0 + warp_n + ni * 8 + (lane & 3) * 2;
            float b0v = 0.f, b1v = 0.f;
            if (BIAS) { b0v = bias[cg]; b1v = bias[cg + 1]; }
            float v0 = acc[mi][ni][0] * alpha + b0v;
            float v1 = acc[mi][ni][1] * alpha + b1v;
            float v2 = acc[mi][ni][2] * alpha + b0v;
            float v3 = acc[mi][ni][3] * alpha + b1v;
            if (RELU) {
                v0 = fmaxf(v0, 0.f); v1 = fmaxf(v1, 0.f);
                v2 = fmaxf(v2, 0.f); v3 = fmaxf(v3, 0.f);
            }
            *(float2*)&C[(size_t)rg * ldc + cg]       = make_float2(v0, v1);
            *(float2*)&C[(size_t)(rg + 8) * ldc + cg] = make_float2(v2, v3);
        }
    }
}

// ---------------- tf32 NT GEMM (single-pass): ctx_vals^T + split-K context ----------------
template<bool BIAS, bool TROUT, bool ATOMIC>
__global__ void __launch_bounds__(256, 2) mma_nt(
    const float* __restrict__ A, const float* __restrict__ B,
    const float* __restrict__ bias, float* __restrict__ C,
    int lda, int ldb, int ldc, int nch, float alpha)
{
    __shared__ float smem[2 * 5120];
    const uint32_t sb = smem_u32(smem);
    const int tid  = threadIdx.x;
    const int wid  = tid >> 5;
    const int lane = tid & 31;
    const int m0 = blockIdx.x * 128;
    const int n0 = blockIdx.y * 128;
    const int warp_m = (wid >> 2) * 64;
    const int warp_n = (wid & 3) * 32;

    A += (size_t)blockIdx.z * nch * 16;
    B += (size_t)blockIdx.z * nch * 16;
    const float* Abase = A + (size_t)m0 * lda;
    const float* Bbase = B + (size_t)n0 * ldb;

    const int r0c = tid >> 2,         s0c = (tid & 3) * 4;
    const int r1c = (tid + 256) >> 2, s1c = ((tid + 256) & 3) * 4;

    float acc[4][4][4];
    #pragma unroll
    for (int i = 0; i < 4; ++i)
        #pragma unroll
        for (int j = 0; j < 4; ++j)
            #pragma unroll
            for (int k = 0; k < 4; ++k) acc[i][j][k] = 0.f;

    const uint32_t aOff = ((warp_m + (lane & 15)) * 20 + (lane >> 4) * 4) * 4;
    const uint32_t bOff = ((warp_n + ((lane >> 4) << 3) + (lane & 7)) * 20 +
                           ((lane >> 3) & 1) * 4) * 4;
    {
        CP_ASYNC(sb + (r0c * 20 + s0c) * 4,        Abase + (size_t)r0c * lda + s0c);
        CP_ASYNC(sb + (r1c * 20 + s1c) * 4,        Abase + (size_t)r1c * lda + s1c);
        CP_ASYNC(sb + (2560 + r0c * 20 + s0c) * 4, Bbase + (size_t)r0c * ldb + s0c);
        CP_ASYNC(sb + (2560 + r1c * 20 + s1c) * 4, Bbase + (size_t)r1c * ldb + s1c);
        CP_COMMIT();
    }
    int st = 0;
    for (int c = 0; c < nch; ++c) {
        if (c + 1 < nch) {
            const int k0 = (c + 1) * 16;
            const uint32_t s = sb + (st ^ 1) * 5120 * 4;
            CP_ASYNC(s + (r0c * 20 + s0c) * 4,        Abase + (size_t)r0c * lda + k0 + s0c);
            CP_ASYNC(s + (r1c * 20 + s1c) * 4,        Abase + (size_t)r1c * lda + k0 + s1c);
            CP_ASYNC(s + (2560 + r0c * 20 + s0c) * 4, Bbase + (size_t)r0c * ldb + k0 + s0c);
            CP_ASYNC(s + (2560 + r1c * 20 + s1c) * 4, Bbase + (size_t)r1c * ldb + k0 + s1c);
            CP_COMMIT();
            asm volatile("cp.async.wait_group 1;");
        } else {
            asm volatile("cp.async.wait_group 0;");
        }
        __syncthreads();

        const uint32_t aB = sb + st * 5120 * 4 + aOff;
        const uint32_t bB = sb + (st * 5120 + 2560) * 4 + bOff;
        #pragma unroll
        for (int ks = 0; ks < 2; ++ks) {
            uint32_t br[8], bh[8];
            LDMX4(br[0], br[1], br[2], br[3], bB + ks * 32);
            LDMX4(br[4], br[5], br[6], br[7], bB + 1280 + ks * 32);
            #pragma unroll
            for (int i = 0; i < 8; ++i) bh[i] = f2tf32(__uint_as_float(br[i]));
            #pragma unroll
            for (int mi = 0; mi < 4; ++mi) {
                uint32_t ar[4], ah[4];
                LDMX4(ar[0], ar[1], ar[2], ar[3], aB + mi * 1280 + ks * 32);
                #pragma unroll
                for (int i = 0; i < 4; ++i) ah[i] = f2tf32(__uint_as_float(ar[i]));
                #pragma unroll
                for (int ni = 0; ni < 4; ++ni)
                    MMA(acc[mi][ni], ah, bh[ni * 2], bh[ni * 2 + 1]);
            }
        }
        __syncthreads();
        st ^= 1;
    }

    #pragma unroll
    for (int mi = 0; mi < 4; ++mi) {
        const int rg = m0 + warp_m + mi * 16 + (lane >> 2);
        #pragma unroll
        for (int ni = 0; ni < 4; ++ni) {
            const int cg = n0 + warp_n + ni * 8 + (lane & 3) * 2;
            float b0v = 0.f, b1v = 0.f;
            if (BIAS) { b0v = bias[cg]; b1v = bias[cg + 1]; }
            float v0 = acc[mi][ni][0] * alpha + b0v;
            float v1 = acc[mi][ni][1] * alpha + b1v;
            float v2 = acc[mi][ni][2] * alpha + b0v;
            float v3 = acc[mi][ni][3] * alpha + b1v;
            if (TROUT) {
                C[(size_t)cg * ldc + rg]           = v0;
                C[(size_t)(cg + 1) * ldc + rg]     = v1;
                C[(size_t)cg * ldc + rg + 8]       = v2;
                C[(size_t)(cg + 1) * ldc + rg + 8] = v3;
            } else if (ATOMIC) {
                atomicAdd(&C[(size_t)rg * ldc + cg],           v0);
                atomicAdd(&C[(size_t)rg * ldc + cg + 1],       v1);
                atomicAdd(&C[(size_t)(rg + 8) * ldc + cg],     v2);
                atomicAdd(&C[(size_t)(rg + 8) * ldc + cg + 1], v3);
            } else {
                *(float2*)&C[(size_t)rg * ldc + cg]       = make_float2(v0, v1);
                *(float2*)&C[(size_t)(rg + 8) * ldc + cg] = make_float2(v2, v3);
            }
        }
    }
}

// ---------------- transpose out[C][R] = in[R][C]^T ----------------
__global__ void transpose_k(const float* __restrict__ in, float* __restrict__ out, int R, int C)
{
    __shared__ float t[32][33];
    const int c0 = blockIdx.x * 32, r0 = blockIdx.y * 32;
    #pragma unroll
    for (int j = 0; j < 32; j += 8) {
        int r = r0 + threadIdx.y + j, c = c0 + threadIdx.x;
        if (r < R && c < C) t[threadIdx.y + j][threadIdx.x] = in[(size_t)r * C + c];
    }
    __syncthreads();
    #pragma unroll
    for (int j = 0; j < 32; j += 8) {
        int r = c0 + threadIdx.y + j, c = r0 + threadIdx.x;
        if (r < C && c < R) out[(size_t)r * R + c] = t[threadIdx.x][threadIdx.y + j];
    }
}

// ---------------- softmax: unnormalized exp in-place + row sums ----------------
__global__ void __launch_bounds__(256) softmax_exp_kernel(
    float* __restrict__ logits, float* __restrict__ rowsum)
{
    const int b = blockIdx.x;
    float4* row = (float4*)(logits + (size_t)b * N_CAND);
    const int n4 = N_CAND / 4;
    __shared__ float red[256];
    float m = -1e30f;
    for (int i = threadIdx.x; i < n4; i += 256) {
        float4 v = row[i];
        m = fmaxf(m, fmaxf(fmaxf(v.x, v.y), fmaxf(v.z, v.w)));
    }
    red[threadIdx.x] = m; __syncthreads();
    for (int s = 128; s; s >>= 1) {
        if (threadIdx.x < s) red[threadIdx.x] = fmaxf(red[threadIdx.x], red[threadIdx.x + s]);
        __syncthreads();
    }
    const float rmax = red[0];
    __syncthreads();
    float sum = 0.f;
    for (int i = threadIdx.x; i < n4; i += 256) {
        float4 v = row[i];
        v.x = __expf(v.x - rmax); v.y = __expf(v.y - rmax);
        v.z = __expf(v.z - rmax); v.w = __expf(v.w - rmax);
        sum += v.x + v.y + v.z + v.w;
        row[i] = v;
    }
    red[threadIdx.x] = sum; __syncthreads();
    for (int s = 128; s; s >>= 1) {
        if (threadIdx.x < s) red[threadIdx.x] += red[threadIdx.x + s];
        __syncthreads();
    }
    if (threadIdx.x == 0) rowsum[b] = red[0];
}

__global__ void zero_kernel(float* __restrict__ p, int n)
{
    int i = blockIdx.x * 256 + threadIdx.x;
    if (i < n) p[i] = 0.f;
}

// ---------------- head ----------------
__global__ void __launch_bounds__(320) head_kernel(
    const float* __restrict__ q, const float* __restrict__ ctx,
    const float* __restrict__ rowsum, const float* __restrict__ hw,
    const float* __restrict__ hb, float* __restrict__ out)
{
    const int b = blockIdx.x;
    const int warp = threadIdx.x >> 5;
    const int lane = threadIdx.x & 31;
    if (warp >= N_CLS) return;
    const float inv = 1.f / rowsum[b];
    float s = 0.f;
    #pragma unroll 4
    for (int d = lane; d < D_MAIN; d += 32)
        s += (q[b * D_MAIN + d] + ctx[b * D_MAIN + d] * inv) * hw[d * N_CLS + warp];
    #pragma unroll
    for (int off = 16; off; off >>= 1) s += __shfl_down_sync(0xFFFFFFFFu, s, off);
    if (lane == 0) out[b * N_CLS + warp] = s + hb[warp];
}

// ---------------- launch ----------------
extern "C" void kernel_launch(void* const* d_in, const int* in_sizes, int n_in,
                              void* d_out, int out_size)
{
    const float* x    = (const float*)d_in[0];
    const float* cand = (const float*)d_in[1];
    const float* w0   = (const float*)d_in[2];
    const float* b0   = (const float*)d_in[3];
    const float* w1   = (const float*)d_in[4];
    const float* b1   = (const float*)d_in[5];
    const float* w2   = (const float*)d_in[6];
    const float* b2   = (const float*)d_in[7];
    const float* tw   = (const float*)d_in[8];
    const float* tb   = (const float*)d_in[9];
    const float* hw   = (const float*)d_in[10];
    const float* hb   = (const float*)d_in[11];
    float* out = (float*)d_out;

    float *qa, *qb, *h, *ctx, *rowsum, *logits, *ctxvT, *w0T, *w1T, *w2T, *twT;
    cudaGetSymbolAddress((void**)&qa, g_qa);
    cudaGetSymbolAddress((void**)&qb, g_qb);
    cudaGetSymbolAddress((void**)&h, g_h);
    cudaGetSymbolAddress((void**)&ctx, g_ctx);
    cudaGetSymbolAddress((void**)&rowsum, g_rowsum);
    cudaGetSymbolAddress((void**)&logits, g_logits);
    cudaGetSymbolAddress((void**)&ctxvT, g_ctxvT);
    cudaGetSymbolAddress((void**)&w0T, g_w0T);
    cudaGetSymbolAddress((void**)&w1T, g_w1T);
    cudaGetSymbolAddress((void**)&w2T, g_w2T);
    cudaGetSymbolAddress((void**)&twT, g_twT);

    __nv_bfloat16 *candH, *candL, *xH, *xL, *w0TH, *w0TL, *w1TH, *w1TL, *w2TH, *w2TL,
                  *aH, *aL, *hH, *hL;
    cudaGetSymbolAddress((void**)&candH, g_candH);
    cudaGetSymbolAddress((void**)&candL, g_candL);
    cudaGetSymbolAddress((void**)&xH, g_xH);
    cudaGetSymbolAddress((void**)&xL, g_xL);
    cudaGetSymbolAddress((void**)&w0TH, g_w0TH);
    cudaGetSymbolAddress((void**)&w0TL, g_w0TL);
    cudaGetSymbolAddress((void**)&w1TH, g_w1TH);
    cudaGetSymbolAddress((void**)&w1TL, g_w1TL);
    cudaGetSymbolAddress((void**)&w2TH, g_w2TH);
    cudaGetSymbolAddress((void**)&w2TL, g_w2TL);
    cudaGetSymbolAddress((void**)&aH, g_aH);
    cudaGetSymbolAddress((void**)&aL, g_aL);
    cudaGetSymbolAddress((void**)&hH, g_hH);
    cudaGetSymbolAddress((void**)&hL, g_hL);

    const float scale = (float)(1.0 / (sqrt(512.0) * 0.2));
    dim3 tb32(32, 8);
    auto spl = [](const float* in, __nv_bfloat16* hi, __nv_bfloat16* lo, int n) {
        int n4 = n / 4;
        split_k<<<(n4 + 255) / 256, 256>>>(in, hi, lo, n4);
    };

    // weight transposes (fp32)
    transpose_k<<<dim3(16, 3), tb32>>>(w0, w0T, D_IN, D_MAIN);
    transpose_k<<<dim3(32, 16), tb32>>>(w1, w1T, D_MAIN, D_BLOCK);
    transpose_k<<<dim3(32, 16), tb32>>>(w1 + D_MAIN*D_BLOCK, w1T + D_BLOCK*D_MAIN, D_MAIN, D_BLOCK);
    transpose_k<<<dim3(16, 32), tb32>>>(w2, w2T, D_BLOCK, D_MAIN);
    transpose_k<<<dim3(16, 32), tb32>>>(w2 + D_BLOCK*D_MAIN, w2T + D_MAIN*D_BLOCK, D_BLOCK, D_MAIN);
    transpose_k<<<dim3(16, 16), tb32>>>(tw, twT, D_MAIN, D_MAIN);

    // bf16 decompositions (weights + inputs)
    spl(x,    xH,   xL,   BQ * D_IN);
    spl(w0T,  w0TH, w0TL, D_MAIN * D_IN);
    spl(w1T,  w1TH, w1TL, 2 * D_BLOCK * D_MAIN);
    spl(w2T,  w2TH, w2TL, 2 * D_MAIN * D_BLOCK);
    spl(cand, candH, candL, N_CAND * D_MAIN);

    // encoder (bf16x3)
    mma_bf16_nt<true,false><<<dim3(8,4), 256>>>(
        xH, xL, w0TH, w0TL, b0, qa, D_IN, D_IN, D_MAIN, 6, 1.f);
    spl(qa, aH, aL, BQ * D_MAIN);
    mma_bf16_nt<true,true><<<dim3(8,8), 256>>>(
        aH, aL, w1TH, w1TL, b1, h, D_MAIN, D_MAIN, D_BLOCK, 32, 1.f);
    spl(h, hH, hL, BQ * D_BLOCK);
    mma_bf16_nt<true,false><<<dim3(8,4), 256>>>(
        hH, hL, w2TH, w2TL, b2, qb, D_BLOCK, D_BLOCK, D_MAIN, 64, 1.f);
    spl(qb, aH, aL, BQ * D_MAIN);
    mma_bf16_nt<true,true><<<dim3(8,8), 256>>>(
        aH, aL, w1TH + (size_t)D_BLOCK*D_MAIN, w1TL + (size_t)D_BLOCK*D_MAIN,
        b1 + D_BLOCK, h, D_MAIN, D_MAIN, D_BLOCK, 32, 1.f);
    spl(h, hH, hL, BQ * D_BLOCK);
    mma_bf16_nt<true,false><<<dim3(8,4), 256>>>(
        hH, hL, w2TH + (size_t)D_MAIN*D_BLOCK, w2TL + (size_t)D_MAIN*D_BLOCK,
        b2 + D_MAIN, qa, D_BLOCK, D_BLOCK, D_MAIN, 64, 1.f);
    spl(qa, aH, aL, BQ * D_MAIN);   // final q hi/lo

    // ctx_vals^T = (cand @ tw + tb)^T  (single tf32, transposed epilogue)
    mma_nt<true,true,false><<<dim3(512,4), 256>>>(
        cand, twT, tb, ctxvT, D_MAIN, D_MAIN, N_CAND, 32, 1.f);

    // logits = scale * q @ cand^T  (bf16x3)
    mma_bf16_nt<false,false><<<dim3(8,512), 256>>>(
        aH, aL, candH, candL, nullptr, logits, D_MAIN, D_MAIN, N_CAND, 32, scale);

    // softmax (unnormalized) + row sums
    softmax_exp_kernel<<<BQ, 256>>>(logits, rowsum);

    // context = expw @ (ctxvT)^T   (split-K=32, atomic accumulate, single tf32)
    zero_kernel<<<(BQ * D_MAIN + 255) / 256, 256>>>(ctx, BQ * D_MAIN);
    mma_nt<false,false,true><<<dim3(8,4,32), 256>>>(
        logits, ctxvT, nullptr, ctx, N_CAND, N_CAND, D_MAIN, 128, 1.f);

    // head
    head_kernel<<<BQ, 320>>>(qa, ctx, rowsum, hw, hb, out);
}